// round 3
// baseline (speedup 1.0000x reference)
#include <cuda_runtime.h>
#include <stdint.h>
#include <math.h>

// Problem shape (fixed for this dataset entry)
#define Bn 4
#define Ln 8192
#define Dn 1024
#define BLn (Bn * Ln)   // 32768 tokens

// ---------------------------------------------------------------------------
// Scratch (device globals: allocation-free per harness rules)
// ---------------------------------------------------------------------------
__device__ float  g_q[(size_t)BLn * Dn];   // 128 MB
__device__ float  g_k[(size_t)BLn * Dn];   // 128 MB
__device__ int    g_src[BLn];              // source token index per compressed slot
__device__ int    g_len[Bn];
__device__ double g_sumP[Bn];

// packed f32x2 FMA: d = a * b + d  (per-lane fp32 rn, 2 lanes per instruction)
#define FMA2(d, a, b) \
    asm("fma.rn.f32x2 %0, %1, %2, %3;" : "=l"(d) : "l"(a), "l"(b), "l"(d))

// B column permutation inside a 128-wide tile row of smem:
// column n lives at float index 32*((n>>1)&3) + 2*(n>>3) + (n&1)
__device__ __forceinline__ int bperm(int n) {
    return 32 * ((n >> 1) & 3) + 2 * (n >> 3) + (n & 1);
}

// ---------------------------------------------------------------------------
// SGEMM via packed f32x2: C[m,n] = sum_k X[m,k] * W[n,k]
// X: 32768x1024, W: 1024x1024.  128x128 tile, BK=8, 256 threads,
// 8x8 per-thread microtile held as 8x4 f32x2 pairs, double-buffered smem.
// A stored duplicated ({a,a} pairs); B stored permuted for conflict-free
// 64-bit pair loads.  blockIdx.z selects (Wq -> g_q) vs (Wk -> g_k).
// ---------------------------------------------------------------------------
__global__ __launch_bounds__(256, 2)
void sgemm_qk(const float* __restrict__ X,
              const float* __restrict__ Wq,
              const float* __restrict__ Wk)
{
    __shared__ float As2[2][8][256];   // duplicated pairs: [2r],[2r+1] = A[r]
    __shared__ float Bs[2][8][128];    // permuted columns

    const float* W = (blockIdx.z == 0) ? Wq : Wk;
    float*       C = (blockIdx.z == 0) ? g_q : g_k;

    const int tid = threadIdx.x;
    const int sr  = tid >> 1;          // 0..127 : tile row loaded by this thread
    const int kc  = (tid & 1) << 2;    // 0 or 4 : k-subcolumn (float4)
    const int bp  = bperm(sr);         // permuted B position for row sr

    const float* aptr = X + ((size_t)blockIdx.y * 128 + sr) * Dn + kc;
    const float* bptr = W + ((size_t)blockIdx.x * 128 + sr) * Dn + kc;

    const int ty = tid >> 4;           // 0..15 : row group (8 rows)
    const int tx = tid & 15;           // 0..15 : col group (8 cols = 4 pairs)

    unsigned long long acc2[8][4];
    #pragma unroll
    for (int i = 0; i < 8; i++) {
        #pragma unroll
        for (int j = 0; j < 4; j++) acc2[i][j] = 0ull;
    }

    float4 a4 = *(const float4*)aptr;
    float4 b4 = *(const float4*)bptr;
    {
        float av[4] = {a4.x, a4.y, a4.z, a4.w};
        float bv[4] = {b4.x, b4.y, b4.z, b4.w};
        #pragma unroll
        for (int q = 0; q < 4; q++) {
            *(float2*)&As2[0][kc + q][2 * sr] = make_float2(av[q], av[q]);
            Bs[0][kc + q][bp] = bv[q];
        }
    }
    __syncthreads();

    int buf = 0;
    #pragma unroll 1
    for (int kt = 0; kt < Dn / 8; kt++) {
        if (kt < Dn / 8 - 1) {
            a4 = *(const float4*)(aptr + (size_t)(kt + 1) * 8);
            b4 = *(const float4*)(bptr + (size_t)(kt + 1) * 8);
        }
        #pragma unroll
        for (int kk = 0; kk < 8; kk++) {
            unsigned long long a2[8], b2[4];
            #pragma unroll
            for (int i = 0; i < 8; i++)
                a2[i] = *(const unsigned long long*)&As2[buf][kk][2 * (ty * 8 + i)];
            #pragma unroll
            for (int j = 0; j < 4; j++)
                b2[j] = *(const unsigned long long*)&Bs[buf][kk][32 * j + 2 * tx];
            #pragma unroll
            for (int i = 0; i < 8; i++) {
                #pragma unroll
                for (int j = 0; j < 4; j++)
                    FMA2(acc2[i][j], a2[i], b2[j]);
            }
        }
        if (kt < Dn / 8 - 1) {
            const int nb = buf ^ 1;
            float av[4] = {a4.x, a4.y, a4.z, a4.w};
            float bv[4] = {b4.x, b4.y, b4.z, b4.w};
            #pragma unroll
            for (int q = 0; q < 4; q++) {
                *(float2*)&As2[nb][kc + q][2 * sr] = make_float2(av[q], av[q]);
                Bs[nb][kc + q][bp] = bv[q];
            }
            __syncthreads();
            buf = nb;
        }
    }

    // Epilogue: acc2[i][j] holds cols (8tx+2j, 8tx+2j+1) of row ty*8+i.
    const size_t row0 = (size_t)blockIdx.y * 128 + ty * 8;
    const int    col0 = blockIdx.x * 128 + tx * 8;
    #pragma unroll
    for (int i = 0; i < 8; i++) {
        float lo0, hi0, lo1, hi1;
        asm("mov.b64 {%0, %1}, %2;" : "=f"(lo0), "=f"(hi0) : "l"(acc2[i][0]));
        asm("mov.b64 {%0, %1}, %2;" : "=f"(lo1), "=f"(hi1) : "l"(acc2[i][1]));
        *(float4*)&C[(row0 + i) * Dn + col0] = make_float4(lo0, hi0, lo1, hi1);
        asm("mov.b64 {%0, %1}, %2;" : "=f"(lo0), "=f"(hi0) : "l"(acc2[i][2]));
        asm("mov.b64 {%0, %1}, %2;" : "=f"(lo1), "=f"(hi1) : "l"(acc2[i][3]));
        *(float4*)&C[(row0 + i) * Dn + col0 + 4] = make_float4(lo0, hi0, lo1, hi1);
    }
}

// ---------------------------------------------------------------------------
// Per-token: ||q_l||, ||k_{l-1}||, q_l . k_{l-1}  ->  p, b  (fp64 reductions)
// One block (128 threads) per token.
// ---------------------------------------------------------------------------
__global__ void props_kernel(float* __restrict__ out_p, float* __restrict__ out_b)
{
    const int t   = blockIdx.x;
    const int l   = t & (Ln - 1);
    const int tid = threadIdx.x;

    if (l == 0) {
        if (tid == 0) { out_p[t] = 1.0f; out_b[t] = 1.0f; }
        return;
    }

    const float4* qr = (const float4*)(g_q + (size_t)t * Dn);
    const float4* kr = (const float4*)(g_k + (size_t)(t - 1) * Dn);

    double sq = 0.0, sk = 0.0, sp = 0.0;
    #pragma unroll
    for (int it = 0; it < 2; it++) {
        const float4 qv = qr[tid + it * 128];
        const float4 kv = kr[tid + it * 128];
        sq += (double)qv.x * qv.x + (double)qv.y * qv.y +
              (double)qv.z * qv.z + (double)qv.w * qv.w;
        sk += (double)kv.x * kv.x + (double)kv.y * kv.y +
              (double)kv.z * kv.z + (double)kv.w * kv.w;
        sp += (double)qv.x * kv.x + (double)qv.y * kv.y +
              (double)qv.z * kv.z + (double)qv.w * kv.w;
    }
    #pragma unroll
    for (int o = 16; o > 0; o >>= 1) {
        sq += __shfl_down_sync(0xffffffffu, sq, o);
        sk += __shfl_down_sync(0xffffffffu, sk, o);
        sp += __shfl_down_sync(0xffffffffu, sp, o);
    }
    __shared__ double sh[3][4];
    const int wid = tid >> 5, lane = tid & 31;
    if (lane == 0) { sh[0][wid] = sq; sh[1][wid] = sk; sh[2][wid] = sp; }
    __syncthreads();
    if (tid == 0) {
        const double SQ = sh[0][0] + sh[0][1] + sh[0][2] + sh[0][3];
        const double SK = sh[1][0] + sh[1][1] + sh[1][2] + sh[1][3];
        const double SP = sh[2][0] + sh[2][1] + sh[2][2] + sh[2][3];
        const float nq = fmaxf(sqrtf((float)SQ), 1e-12f);
        const float nk = fmaxf(sqrtf((float)SK), 1e-12f);
        const float cs = (float)SP / (nq * nk);
        const float pv = 0.5f * (1.0f - cs);
        out_p[t] = pv;
        out_b[t] = (pv >= 0.5f) ? 1.0f : 0.0f;
    }
}

// ---------------------------------------------------------------------------
// Per-batch scan of b: compressed slots, P_down, lengths, sum(p).
// ---------------------------------------------------------------------------
__global__ void scan_kernel(const float* __restrict__ p_arr,
                            const float* __restrict__ b_arr,
                            float* __restrict__ P_down,
                            float* __restrict__ out_len)
{
    const int batch = blockIdx.x;
    const int tid   = threadIdx.x;          // 256
    const float* bb = b_arr + batch * Ln;
    const float* pp = p_arr + batch * Ln;
    const int base  = tid * 32;

    int    cnt  = 0;
    double sump = 0.0;
    #pragma unroll 8
    for (int j = 0; j < 32; j++) {
        const float bv = bb[base + j];
        cnt  += (bv > 0.5f) ? 1 : 0;
        sump += (double)pp[base + j];
    }

    const int lane = tid & 31, wid = tid >> 5;
    int v = cnt;
    #pragma unroll
    for (int o = 1; o < 32; o <<= 1) {
        const int n = __shfl_up_sync(0xffffffffu, v, o);
        if (lane >= o) v += n;
    }
    __shared__ int wsum[8], woff[8], stotal;
    if (lane == 31) wsum[wid] = v;
    __syncthreads();
    if (tid == 0) {
        int s = 0;
        for (int w = 0; w < 8; w++) { woff[w] = s; s += wsum[w]; }
        stotal = s;
    }
    __syncthreads();

    int slot = woff[wid] + v - cnt;          // exclusive prefix
    const int total = stotal;

    for (int j = 0; j < 32; j++) {
        const float bv = bb[base + j];
        if (bv > 0.5f) {
            const int l = base + j;
            g_src[batch * Ln + slot]  = l;
            P_down[batch * Ln + slot] = pp[l];
            slot++;
        }
    }
    for (int s = total + tid; s < Ln; s += 256)
        P_down[batch * Ln + s] = 0.0f;

    #pragma unroll
    for (int o = 16; o > 0; o >>= 1)
        sump += __shfl_down_sync(0xffffffffu, sump, o);
    __shared__ double psh[8];
    if (lane == 0) psh[wid] = sump;
    __syncthreads();
    if (tid == 0) {
        double s = 0.0;
        for (int w = 0; w < 8; w++) s += psh[w];
        g_sumP[batch]   = s;
        g_len[batch]    = total;
        out_len[batch]  = (float)total;
    }
}

// ---------------------------------------------------------------------------
// Gather: x_down[i, j] = (j < len_i) ? x[i, src] : 0.   One block per row.
// ---------------------------------------------------------------------------
__global__ void gather_kernel(const float* __restrict__ x, float* __restrict__ x_down)
{
    const int row   = blockIdx.x;            // 0..32767
    const int batch = row >> 13;
    const int j     = row & (Ln - 1);
    const int tid   = threadIdx.x;            // 256, 1 float4 each

    float4* dst = (float4*)(x_down + (size_t)row * Dn);
    if (j < g_len[batch]) {
        const int src = g_src[row];
        const float4* s = (const float4*)(x + (size_t)(batch * Ln + src) * Dn);
        dst[tid] = s[tid];
    } else {
        dst[tid] = make_float4(0.f, 0.f, 0.f, 0.f);
    }
}

// ---------------------------------------------------------------------------
// ratio_loss = N/(N-1) * ((N-1)*F*G + (1-F)*(1-G)),  N = 6
// ---------------------------------------------------------------------------
__global__ void finalize_kernel(float* __restrict__ o_loss)
{
    double sb = 0.0, sp = 0.0;
    for (int i = 0; i < Bn; i++) { sb += (double)g_len[i]; sp += g_sumP[i]; }
    const double F = sb / (double)BLn;
    const double G = sp / (double)BLn;
    const double N = 6.0;
    o_loss[0] = (float)(N / (N - 1.0) * ((N - 1.0) * F * G + (1.0 - F) * (1.0 - G)));
}

// ---------------------------------------------------------------------------
// Launch. Output layout (f32): x_down | P_down | b | p | lengths | ratio_loss
// ---------------------------------------------------------------------------
extern "C" void kernel_launch(void* const* d_in, const int* in_sizes, int n_in,
                              void* d_out, int out_size)
{
    const float* x  = (const float*)d_in[0];
    const float* Wq = (const float*)d_in[1];
    const float* Wk = (const float*)d_in[2];

    float* out    = (float*)d_out;
    float* o_xd   = out;
    float* o_P    = out + (size_t)BLn * Dn;
    float* o_b    = o_P + BLn;
    float* o_p    = o_b + BLn;
    float* o_len  = o_p + BLn;
    float* o_loss = o_len + Bn;

    dim3 ggrid(Dn / 128, BLn / 128, 2);   // (8, 256, 2)
    sgemm_qk<<<ggrid, 256>>>(x, Wq, Wk);
    props_kernel<<<BLn, 128>>>(o_p, o_b);
    scan_kernel<<<Bn, 256>>>(o_p, o_b, o_P, o_len);
    gather_kernel<<<BLn, 256>>>(x, o_xd);
    finalize_kernel<<<1, 1>>>(o_loss);
}

// round 4
// speedup vs baseline: 1.3745x; 1.3745x over previous
#include <cuda_runtime.h>
#include <cuda_bf16.h>
#include <stdint.h>
#include <math.h>

// Problem shape (fixed)
#define Bn 4
#define Ln 8192
#define Dn 1024
#define BLn (Bn * Ln)   // 32768 tokens

// ---------------------------------------------------------------------------
// Scratch (device globals)
// ---------------------------------------------------------------------------
__device__ float  g_q[(size_t)BLn * Dn];               // 128 MB
__device__ float  g_k[(size_t)BLn * Dn];               // 128 MB
__device__ __nv_bfloat16 g_xb[3][(size_t)BLn * Dn];   // 192 MB (x splits)
__device__ __nv_bfloat16 g_wb[2][3][(size_t)Dn * Dn]; // 12 MB  (Wq/Wk splits)
__device__ int    g_src[BLn];
__device__ int    g_len[Bn];
__device__ double g_sumP[Bn];

// ---------------------------------------------------------------------------
// helpers
// ---------------------------------------------------------------------------
__device__ __forceinline__ uint32_t cvta_shared_u32(const void* p) {
    uint32_t r;
    asm("{ .reg .u64 t; cvta.to.shared.u64 t, %1; cvt.u32.u64 %0, t; }"
        : "=r"(r) : "l"(p));
    return r;
}
#define LDMATRIX_X4(r0, r1, r2, r3, addr)                                  \
    asm volatile("ldmatrix.sync.aligned.m8n8.x4.shared.b16 {%0,%1,%2,%3}, [%4];" \
                 : "=r"(r0), "=r"(r1), "=r"(r2), "=r"(r3) : "r"(addr))
#define MMA16816(c0, c1, c2, c3, a0, a1, a2, a3, b0, b1)                   \
    asm volatile("mma.sync.aligned.m16n8k16.row.col.f32.bf16.bf16.f32 "   \
                 "{%0,%1,%2,%3}, {%4,%5,%6,%7}, {%8,%9}, {%0,%1,%2,%3};"  \
                 : "+f"(c0), "+f"(c1), "+f"(c2), "+f"(c3)                  \
                 : "r"(a0), "r"(a1), "r"(a2), "r"(a3), "r"(b0), "r"(b1))
#define CP_ASYNC16(saddr, gaddr)                                           \
    asm volatile("cp.async.cg.shared.global [%0], [%1], 16;"               \
                 :: "r"(saddr), "l"(gaddr))

// ---------------------------------------------------------------------------
// Split kernel: f32 -> 3 exact bf16 splits.  mode 0: x, 1: Wq, 2: Wk
// ---------------------------------------------------------------------------
__global__ void split_kernel(const float* __restrict__ src, int mode, int n4)
{
    int i = blockIdx.x * blockDim.x + threadIdx.x;
    if (i >= n4) return;
    __nv_bfloat16 *d0, *d1, *d2;
    if (mode == 0)      { d0 = g_xb[0];    d1 = g_xb[1];    d2 = g_xb[2]; }
    else if (mode == 1) { d0 = g_wb[0][0]; d1 = g_wb[0][1]; d2 = g_wb[0][2]; }
    else                { d0 = g_wb[1][0]; d1 = g_wb[1][1]; d2 = g_wb[1][2]; }

    const float4 v = ((const float4*)src)[i];
    float a[4] = {v.x, v.y, v.z, v.w};
    unsigned short s0[4], s1[4], s2[4];
    #pragma unroll
    for (int c = 0; c < 4; c++) {
        const float f = a[c];
        const __nv_bfloat16 h0 = __float2bfloat16_rn(f);
        const float r1 = f - __bfloat162float(h0);
        const __nv_bfloat16 h1 = __float2bfloat16_rn(r1);
        const float r2 = r1 - __bfloat162float(h1);
        const __nv_bfloat16 h2 = __float2bfloat16_rn(r2);
        s0[c] = __bfloat16_as_ushort(h0);
        s1[c] = __bfloat16_as_ushort(h1);
        s2[c] = __bfloat16_as_ushort(h2);
    }
    uint2 u0, u1, u2;
    u0.x = (uint32_t)s0[0] | ((uint32_t)s0[1] << 16);
    u0.y = (uint32_t)s0[2] | ((uint32_t)s0[3] << 16);
    u1.x = (uint32_t)s1[0] | ((uint32_t)s1[1] << 16);
    u1.y = (uint32_t)s1[2] | ((uint32_t)s1[3] << 16);
    u2.x = (uint32_t)s2[0] | ((uint32_t)s2[1] << 16);
    u2.y = (uint32_t)s2[2] | ((uint32_t)s2[3] << 16);
    ((uint2*)d0)[i] = u0;
    ((uint2*)d1)[i] = u1;
    ((uint2*)d2)[i] = u2;
}

// ---------------------------------------------------------------------------
// HMMA bf16x3 GEMM:  C[m,n] = sum_k X[m,k] * W[n,k]  via 6 bf16 products.
// Tile 128x128, BK=32, 256 threads (8 warps as 2x4), warp tile 64x32.
// SMEM per buffer: A 3 splits x 128 rows x 32 bf16 (64B rows, swizzled),
// B same.  Double-buffered with cp.async.
// grid = (8 n-tiles, 256 m-tiles, 2 gemms).
// ---------------------------------------------------------------------------
#define SPLIT_BYTES 8192                  // 128 rows * 64 B
#define SIDE_BYTES  (3 * SPLIT_BYTES)     // 24576
#define BUF_BYTES   (2 * SIDE_BYTES)      // 49152 (A side + B side)
#define GEMM_SMEM   (2 * BUF_BYTES)       // 98304

// swizzled byte offset of 16B unit u (0..3) in row r (64B rows)
__device__ __forceinline__ uint32_t sw_off(int r, int u) {
    return (uint32_t)(64 * r + 16 * ((u + (r >> 1)) & 3));
}

__global__ __launch_bounds__(256)
void hgemm_kernel()
{
    extern __shared__ char smem[];
    const uint32_t sbase = cvta_shared_u32(smem);

    const int tid  = threadIdx.x;
    const int wid  = tid >> 5;
    const int lane = tid & 31;
    const int wm   = wid & 1;          // 0..1 : 64-row half
    const int wn   = wid >> 1;         // 0..3 : 32-col quarter
    const int tn = blockIdx.x, tm = blockIdx.y, gz = blockIdx.z;

    const int j    = lane >> 3;        // ldmatrix matrix id 0..3
    const int rlow = lane & 7;

    // ldmatrix row indices (within the 128-row tile)
    int rA[4], rB[2];
    #pragma unroll
    for (int mt = 0; mt < 4; mt++)
        rA[mt] = wm * 64 + mt * 16 + (j & 1) * 8 + rlow;
    #pragma unroll
    for (int g = 0; g < 2; g++)
        rB[g] = wn * 32 + g * 16 + (j & 1) * 8 + rlow;
    const int jhi = j >> 1;            // k-halving bit of the x4 load

    float acc[4][4][4];
    #pragma unroll
    for (int mt = 0; mt < 4; mt++)
        #pragma unroll
        for (int nt = 0; nt < 4; nt++)
            #pragma unroll
            for (int e = 0; e < 4; e++) acc[mt][nt][e] = 0.0f;

    // gmem bases
    const char* xbase = (const char*)&g_xb[0][0] + (size_t)(tm * 128) * (Dn * 2);
    const char* wbase = (const char*)&g_wb[gz][0][0] + (size_t)(tn * 128) * (Dn * 2);
    const size_t XSPL = (size_t)BLn * Dn * 2;
    const size_t WSPL = (size_t)Dn * Dn * 2;

    // loader: 12 x 16B units per thread per chunk
    // unit v: side (A/B), split s, row r, k-unit u
    int  l_side[12], l_s[12], l_r[12], l_u[12];
    #pragma unroll
    for (int i = 0; i < 12; i++) {
        const int v    = tid + i * 256;
        const int side = v >= 1536;
        const int w    = side ? v - 1536 : v;
        l_side[i] = side;
        l_s[i]    = w >> 9;
        l_r[i]    = (w >> 2) & 127;
        l_u[i]    = w & 3;
    }

    #define LOAD_CHUNK(buf, c)                                                  \
    do {                                                                        \
        const uint32_t bb = sbase + (buf) * BUF_BYTES;                          \
        _Pragma("unroll")                                                       \
        for (int i = 0; i < 12; i++) {                                          \
            const uint32_t sa = bb + l_side[i] * SIDE_BYTES +                   \
                                l_s[i] * SPLIT_BYTES + sw_off(l_r[i], l_u[i]);  \
            const char* ga = (l_side[i] ? wbase + l_s[i] * WSPL                 \
                                        : xbase + l_s[i] * XSPL) +              \
                             (size_t)l_r[i] * (Dn * 2) + (c) * 64 + l_u[i] * 16;\
            CP_ASYNC16(sa, ga);                                                 \
        }                                                                       \
        asm volatile("cp.async.commit_group;");                                 \
    } while (0)

    LOAD_CHUNK(0, 0);

    const int NCH = Dn / 32;   // 32 chunks
    for (int c = 0; c < NCH; c++) {
        const int buf = c & 1;
        if (c + 1 < NCH) {
            LOAD_CHUNK(buf ^ 1, c + 1);
            asm volatile("cp.async.wait_group 1;");
        } else {
            asm volatile("cp.async.wait_group 0;");
        }
        __syncthreads();

        const uint32_t aB = sbase + buf * BUF_BYTES;
        const uint32_t bB = aB + SIDE_BYTES;

        #pragma unroll
        for (int ks = 0; ks < 2; ks++) {
            // B fragments for all 3 splits: bfr[s][nt][2]
            uint32_t bfr[3][4][2];
            #pragma unroll
            for (int s = 0; s < 3; s++) {
                #pragma unroll
                for (int g = 0; g < 2; g++) {
                    uint32_t r0, r1, r2, r3;
                    const uint32_t addr = bB + s * SPLIT_BYTES + 64 * rB[g] +
                        16 * (((2 * ks + jhi) + (rB[g] >> 1)) & 3);
                    LDMATRIX_X4(r0, r1, r2, r3, addr);
                    bfr[s][2 * g + 0][0] = r0; bfr[s][2 * g + 0][1] = r2;
                    bfr[s][2 * g + 1][0] = r1; bfr[s][2 * g + 1][1] = r3;
                }
            }
            // A per split, then its product set
            #pragma unroll
            for (int pa = 0; pa < 3; pa++) {
                uint32_t afr[4][4];
                #pragma unroll
                for (int mt = 0; mt < 4; mt++) {
                    const uint32_t addr = aB + pa * SPLIT_BYTES + 64 * rA[mt] +
                        16 * (((2 * ks + jhi) + (rA[mt] >> 1)) & 3);
                    LDMATRIX_X4(afr[mt][0], afr[mt][1], afr[mt][2], afr[mt][3], addr);
                }
                const int npb = (pa == 0) ? 3 : (pa == 1) ? 2 : 1;
                for (int pb = 0; pb < npb; pb++) {
                    #pragma unroll
                    for (int mt = 0; mt < 4; mt++)
                        #pragma unroll
                        for (int nt = 0; nt < 4; nt++)
                            MMA16816(acc[mt][nt][0], acc[mt][nt][1],
                                     acc[mt][nt][2], acc[mt][nt][3],
                                     afr[mt][0], afr[mt][1], afr[mt][2], afr[mt][3],
                                     bfr[pb][nt][0], bfr[pb][nt][1]);
                }
            }
        }
        __syncthreads();
    }

    // epilogue
    float* C = (gz == 0) ? g_q : g_k;
    const int rowb = tm * 128 + wm * 64 + (lane >> 2);
    const int colb = tn * 128 + wn * 32 + 2 * (lane & 3);
    #pragma unroll
    for (int mt = 0; mt < 4; mt++) {
        #pragma unroll
        for (int nt = 0; nt < 4; nt++) {
            const size_t r0 = (size_t)(rowb + mt * 16) * Dn + colb + nt * 8;
            *(float2*)&C[r0]            = make_float2(acc[mt][nt][0], acc[mt][nt][1]);
            *(float2*)&C[r0 + 8 * Dn]   = make_float2(acc[mt][nt][2], acc[mt][nt][3]);
        }
    }
    #undef LOAD_CHUNK
}

// ---------------------------------------------------------------------------
// Per-token props: p, b  (fp64 reductions)
// ---------------------------------------------------------------------------
__global__ void props_kernel(float* __restrict__ out_p, float* __restrict__ out_b)
{
    const int t   = blockIdx.x;
    const int l   = t & (Ln - 1);
    const int tid = threadIdx.x;

    if (l == 0) {
        if (tid == 0) { out_p[t] = 1.0f; out_b[t] = 1.0f; }
        return;
    }
    const float4* qr = (const float4*)(g_q + (size_t)t * Dn);
    const float4* kr = (const float4*)(g_k + (size_t)(t - 1) * Dn);

    double sq = 0.0, sk = 0.0, sp = 0.0;
    #pragma unroll
    for (int it = 0; it < 2; it++) {
        const float4 qv = qr[tid + it * 128];
        const float4 kv = kr[tid + it * 128];
        sq += (double)qv.x * qv.x + (double)qv.y * qv.y +
              (double)qv.z * qv.z + (double)qv.w * qv.w;
        sk += (double)kv.x * kv.x + (double)kv.y * kv.y +
              (double)kv.z * kv.z + (double)kv.w * kv.w;
        sp += (double)qv.x * kv.x + (double)qv.y * kv.y +
              (double)qv.z * kv.z + (double)qv.w * kv.w;
    }
    #pragma unroll
    for (int o = 16; o > 0; o >>= 1) {
        sq += __shfl_down_sync(0xffffffffu, sq, o);
        sk += __shfl_down_sync(0xffffffffu, sk, o);
        sp += __shfl_down_sync(0xffffffffu, sp, o);
    }
    __shared__ double sh[3][4];
    const int wid = tid >> 5, lane = tid & 31;
    if (lane == 0) { sh[0][wid] = sq; sh[1][wid] = sk; sh[2][wid] = sp; }
    __syncthreads();
    if (tid == 0) {
        const double SQ = sh[0][0] + sh[0][1] + sh[0][2] + sh[0][3];
        const double SK = sh[1][0] + sh[1][1] + sh[1][2] + sh[1][3];
        const double SP = sh[2][0] + sh[2][1] + sh[2][2] + sh[2][3];
        const float nq = fmaxf(sqrtf((float)SQ), 1e-12f);
        const float nk = fmaxf(sqrtf((float)SK), 1e-12f);
        const float cs = (float)SP / (nq * nk);
        const float pv = 0.5f * (1.0f - cs);
        out_p[t] = pv;
        out_b[t] = (pv >= 0.5f) ? 1.0f : 0.0f;
    }
}

// ---------------------------------------------------------------------------
// Per-batch scan of b
// ---------------------------------------------------------------------------
__global__ void scan_kernel(const float* __restrict__ p_arr,
                            const float* __restrict__ b_arr,
                            float* __restrict__ P_down,
                            float* __restrict__ out_len)
{
    const int batch = blockIdx.x;
    const int tid   = threadIdx.x;
    const float* bb = b_arr + batch * Ln;
    const float* pp = p_arr + batch * Ln;
    const int base  = tid * 32;

    int    cnt  = 0;
    double sump = 0.0;
    #pragma unroll 8
    for (int jj = 0; jj < 32; jj++) {
        const float bv = bb[base + jj];
        cnt  += (bv > 0.5f) ? 1 : 0;
        sump += (double)pp[base + jj];
    }
    const int lane = tid & 31, wid = tid >> 5;
    int v = cnt;
    #pragma unroll
    for (int o = 1; o < 32; o <<= 1) {
        const int n = __shfl_up_sync(0xffffffffu, v, o);
        if (lane >= o) v += n;
    }
    __shared__ int wsum[8], woff[8], stotal;
    if (lane == 31) wsum[wid] = v;
    __syncthreads();
    if (tid == 0) {
        int s = 0;
        for (int w = 0; w < 8; w++) { woff[w] = s; s += wsum[w]; }
        stotal = s;
    }
    __syncthreads();

    int slot = woff[wid] + v - cnt;
    const int total = stotal;

    for (int jj = 0; jj < 32; jj++) {
        const float bv = bb[base + jj];
        if (bv > 0.5f) {
            const int l = base + jj;
            g_src[batch * Ln + slot]  = l;
            P_down[batch * Ln + slot] = pp[l];
            slot++;
        }
    }
    for (int s = total + tid; s < Ln; s += 256)
        P_down[batch * Ln + s] = 0.0f;

    #pragma unroll
    for (int o = 16; o > 0; o >>= 1)
        sump += __shfl_down_sync(0xffffffffu, sump, o);
    __shared__ double psh[8];
    if (lane == 0) psh[wid] = sump;
    __syncthreads();
    if (tid == 0) {
        double s = 0.0;
        for (int w = 0; w < 8; w++) s += psh[w];
        g_sumP[batch]  = s;
        g_len[batch]   = total;
        out_len[batch] = (float)total;
    }
}

// ---------------------------------------------------------------------------
// Gather x_down
// ---------------------------------------------------------------------------
__global__ void gather_kernel(const float* __restrict__ x, float* __restrict__ x_down)
{
    const int row   = blockIdx.x;
    const int batch = row >> 13;
    const int jj    = row & (Ln - 1);
    const int tid   = threadIdx.x;

    float4* dst = (float4*)(x_down + (size_t)row * Dn);
    if (jj < g_len[batch]) {
        const int src = g_src[row];
        const float4* s = (const float4*)(x + (size_t)(batch * Ln + src) * Dn);
        dst[tid] = s[tid];
    } else {
        dst[tid] = make_float4(0.f, 0.f, 0.f, 0.f);
    }
}

__global__ void finalize_kernel(float* __restrict__ o_loss)
{
    double sb = 0.0, sp = 0.0;
    for (int i = 0; i < Bn; i++) { sb += (double)g_len[i]; sp += g_sumP[i]; }
    const double F = sb / (double)BLn;
    const double G = sp / (double)BLn;
    const double N = 6.0;
    o_loss[0] = (float)(N / (N - 1.0) * ((N - 1.0) * F * G + (1.0 - F) * (1.0 - G)));
}

// ---------------------------------------------------------------------------
// Launch. Output layout (f32): x_down | P_down | b | p | lengths | ratio_loss
// ---------------------------------------------------------------------------
extern "C" void kernel_launch(void* const* d_in, const int* in_sizes, int n_in,
                              void* d_out, int out_size)
{
    const float* x  = (const float*)d_in[0];
    const float* Wq = (const float*)d_in[1];
    const float* Wk = (const float*)d_in[2];

    float* out    = (float*)d_out;
    float* o_xd   = out;
    float* o_P    = out + (size_t)BLn * Dn;
    float* o_b    = o_P + BLn;
    float* o_p    = o_b + BLn;
    float* o_len  = o_p + BLn;
    float* o_loss = o_len + Bn;

    static int smem_set = 0;
    if (!smem_set) {
        cudaFuncSetAttribute(hgemm_kernel,
                             cudaFuncAttributeMaxDynamicSharedMemorySize, GEMM_SMEM);
        smem_set = 1;
    }

    split_kernel<<<(BLn * Dn / 4 + 255) / 256, 256>>>(x, 0, BLn * Dn / 4);
    split_kernel<<<(Dn * Dn / 4 + 255) / 256, 256>>>(Wq, 1, Dn * Dn / 4);
    split_kernel<<<(Dn * Dn / 4 + 255) / 256, 256>>>(Wk, 2, Dn * Dn / 4);

    hgemm_kernel<<<dim3(8, 256, 2), 256, GEMM_SMEM>>>();

    props_kernel<<<BLn, 128>>>(o_p, o_b);
    scan_kernel<<<Bn, 256>>>(o_p, o_b, o_P, o_len);
    gather_kernel<<<BLn, 256>>>(x, o_xd);
    finalize_kernel<<<1, 1>>>(o_loss);
}